// round 6
// baseline (speedup 1.0000x reference)
#include <cuda_runtime.h>
#include <math.h>
#include <float.h>

// Fixed problem shapes
#define BB 2
#define VV 3
#define CC 16
#define HH 128
#define WW 160
#define DD 48
#define HWW (HH*WW)            // 20480
#define NPIX (BB*HWW)          // 40960
#define BDHW (BB*DD*HWW)       // 1966080
#define NV (VV-1)              // 2 source views

// Output layout
#define OFF_DEPTH 0
#define OFF_CONF  (NPIX)
#define OFF_PROB  (2*NPIX)
#define OFF_VW    (2*NPIX + BDHW)

// -------- scratch --------
__device__ float g_feat_t[(size_t)BB*VV*HWW*CC];   // [b][v][h][w][c]
__device__ float g_sim[(size_t)NV*BDHW];           // [view][b][d][h][w]
__device__ float g_simil[BDHW];
__device__ float g_proj[NV*BB*12];
__device__ float g_reg[28];
// PWL representation of the pixelwise MLP (function of scalar sim)
__device__ float g_pwl_t[16];        // sorted breakpoints (float)
__device__ float g_pwl_ab[17*16];    // per interval i: alpha[8] then beta[8]
__device__ float g_pwl_w2[9];        // w2[8], b2

// ======================= prep =======================
__device__ void mat4_mul(const double* A, const double* B, double* Cm) {
    for (int r = 0; r < 4; r++)
        for (int c = 0; c < 4; c++) {
            double s = 0.0;
            for (int k = 0; k < 4; k++) s += A[r*4+k] * B[k*4+c];
            Cm[r*4+c] = s;
        }
}

__device__ void compose_proj(const float* p, double* out) {
    const float* E = p;
    const float* K = p + 16;
    for (int i = 0; i < 16; i++) out[i] = (double)E[i];
    for (int r = 0; r < 3; r++)
        for (int c = 0; c < 4; c++) {
            double s = 0.0;
            for (int k = 0; k < 3; k++) s += (double)K[r*4+k] * (double)E[k*4+c];
            out[r*4+c] = s;
        }
}

__device__ void inv4(const double* A, double* out) {
    double M[4][8];
    for (int i = 0; i < 4; i++)
        for (int j = 0; j < 4; j++) { M[i][j] = A[i*4+j]; M[i][4+j] = (i == j) ? 1.0 : 0.0; }
    for (int col = 0; col < 4; col++) {
        int piv = col;
        for (int r = col + 1; r < 4; r++)
            if (fabs(M[r][col]) > fabs(M[piv][col])) piv = r;
        if (piv != col)
            for (int j = 0; j < 8; j++) { double t = M[col][j]; M[col][j] = M[piv][j]; M[piv][j] = t; }
        double pv = M[col][col];
        for (int j = 0; j < 8; j++) M[col][j] /= pv;
        for (int r = 0; r < 4; r++) {
            if (r == col) continue;
            double f = M[r][col];
            for (int j = 0; j < 8; j++) M[r][j] -= f * M[col][j];
        }
    }
    for (int i = 0; i < 4; i++)
        for (int j = 0; j < 4; j++) out[i*4+j] = M[i][4+j];
}

__global__ void prep_kernel(const float* proj,
                            const float* w0, const float* g0, const float* b0,
                            const float* m0, const float* v0,
                            const float* w1, const float* g1, const float* b1,
                            const float* m1, const float* v1,
                            const float* w2, const float* b2,
                            const float* reg_w, const float* reg_b) {
    if (blockIdx.x != 0 || threadIdx.x != 0) return;
    for (int b = 0; b < BB; b++) {
        double refc[16], refi[16];
        compose_proj(proj + (size_t)(b*VV + 0)*2*16, refc);
        inv4(refc, refi);
        for (int v = 1; v < VV; v++) {
            double srcc[16], P[16];
            compose_proj(proj + (size_t)(b*VV + v)*2*16, srcc);
            mat4_mul(srcc, refi, P);
            float* dst = g_proj + ((v-1)*BB + b)*12;
            for (int r = 0; r < 3; r++)
                for (int c = 0; c < 3; c++) dst[r*3+c] = (float)P[r*4+c];
            dst[9]  = (float)P[0*4+3];
            dst[10] = (float)P[1*4+3];
            dst[11] = (float)P[2*4+3];
        }
    }

    // ---- fold BN into float weights (same rounding as before) ----
    float fw0[16], fc0[16], fw1[8][16], fc1[8], fw2[8];
    for (int o = 0; o < 16; o++) {
        double s = (double)g0[o] / sqrt((double)v0[o] + 1e-5);
        fw0[o] = (float)((double)w0[o] * s);
        fc0[o] = (float)((double)b0[o] - (double)m0[o] * s);
    }
    for (int j = 0; j < 8; j++) {
        double s = (double)g1[j] / sqrt((double)v1[j] + 1e-5);
        for (int o = 0; o < 16; o++)
            fw1[j][o] = (float)((double)w1[j*16+o] * s);
        fc1[j] = (float)((double)b1[j] - (double)m1[j] * s);
        fw2[j] = w2[j];
    }

    // ---- build PWL tables: breakpoints + per-interval (alpha, beta) ----
    double t[16];
    int    ord[16];
    for (int o = 0; o < 16; o++) {
        if (fw0[o] != 0.f) t[o] = -(double)fc0[o] / (double)fw0[o];
        else               t[o] = DBL_MAX;   // never crossed via s
        ord[o] = o;
    }
    // insertion sort ord by t ascending
    for (int i = 1; i < 16; i++) {
        int k = ord[i]; double tv = t[k]; int j = i - 1;
        while (j >= 0 && t[ord[j]] > tv) { ord[j+1] = ord[j]; j--; }
        ord[j+1] = k;
    }
    for (int k = 0; k < 16; k++) {
        double tv = t[ord[k]];
        g_pwl_t[k] = (tv >= DBL_MAX) ? FLT_MAX : (float)tv;
    }
    int pos[16];
    for (int k = 0; k < 16; k++) pos[ord[k]] = k;

    // interval i: s is strictly greater than exactly the i smallest breakpoints
    for (int i = 0; i <= 16; i++) {
        for (int j = 0; j < 8; j++) {
            double alpha = 0.0, beta = (double)fc1[j];
            for (int o = 0; o < 16; o++) {
                bool active;
                if (fw0[o] > 0.f)      active = (pos[o] < i);
                else if (fw0[o] < 0.f) active = (pos[o] >= i);
                else                   active = (fc0[o] > 0.f);  // constant unit
                if (active) {
                    alpha += (double)fw1[j][o] * (double)fw0[o];
                    beta  += (double)fw1[j][o] * (double)fc0[o];
                }
            }
            g_pwl_ab[i*16 + j]     = (float)alpha;
            g_pwl_ab[i*16 + 8 + j] = (float)beta;
        }
    }
    for (int j = 0; j < 8; j++) g_pwl_w2[j] = fw2[j];
    g_pwl_w2[8] = b2[0];

    for (int k = 0; k < 27; k++) g_reg[k] = reg_w[k];
    g_reg[27] = reg_b[0];
}

// ======================= feature transpose to [b][v][h][w][c] =======================
__global__ void transpose_kernel(const float* __restrict__ feat) {
    int idx = blockIdx.x * blockDim.x + threadIdx.x;
    if (idx >= BB*VV*HWW) return;
    int p  = idx % HWW;
    int bv = idx / HWW;
    const float* src = feat + (size_t)bv * CC * HWW + p;
    float v[CC];
#pragma unroll
    for (int c = 0; c < CC; c++) v[c] = src[(size_t)c * HWW];
    float4* dst = (float4*)(g_feat_t + ((size_t)bv * HWW + p) * CC);
    dst[0] = make_float4(v[0],  v[1],  v[2],  v[3]);
    dst[1] = make_float4(v[4],  v[5],  v[6],  v[7]);
    dst[2] = make_float4(v[8],  v[9],  v[10], v[11]);
    dst[3] = make_float4(v[12], v[13], v[14], v[15]);
}

// helper: coords for one depth
struct Coords {
    float x0f, y0f, fx, fy;
    int ix0, ix1, iy0, iy1;
    float vx0, vx1, vy0, vy1;
};
__device__ __forceinline__ Coords proj_coords(float dep, float rx, float ry, float rz,
                                              float tx, float ty, float tz) {
    Coords c;
    float X = fmaf(rx, dep, tx);
    float Y = fmaf(ry, dep, ty);
    float Z = fmaf(rz, dep, tz);
    float px = X / Z;            // exact IEEE division (argmax-sensitive)
    float py = Y / Z;
    c.x0f = floorf(px); c.y0f = floorf(py);
    c.fx = px - c.x0f;  c.fy = py - c.y0f;
    c.vx0 = (c.x0f >= 0.f       && c.x0f       <= (float)(WW-1)) ? 1.f : 0.f;
    c.vx1 = (c.x0f + 1.f >= 0.f && c.x0f + 1.f <= (float)(WW-1)) ? 1.f : 0.f;
    c.vy0 = (c.y0f >= 0.f       && c.y0f       <= (float)(HH-1)) ? 1.f : 0.f;
    c.vy1 = (c.y0f + 1.f >= 0.f && c.y0f + 1.f <= (float)(HH-1)) ? 1.f : 0.f;
    c.ix0 = (int)fminf(fmaxf(c.x0f,       0.f), (float)(WW-1));
    c.ix1 = (int)fminf(fmaxf(c.x0f + 1.f, 0.f), (float)(WW-1));
    c.iy0 = (int)fminf(fmaxf(c.y0f,       0.f), (float)(HH-1));
    c.iy1 = (int)fminf(fmaxf(c.y0f + 1.f, 0.f), (float)(HH-1));
    return c;
}

// full 16-ch dot grouped as ((q0+q1)+(q2+q3)) -- matches butterfly order
__device__ __forceinline__ float full_dot(const float* fp, const float* rp) {
    float part[4];
#pragma unroll
    for (int qq = 0; qq < 4; qq++) {
        float4 f = ((const float4*)fp)[qq];
        float4 r = ((const float4*)rp)[qq];
        part[qq] = fmaf(f.x, r.x, fmaf(f.y, r.y, fmaf(f.z, r.z, f.w * r.w)));
    }
    return (part[0] + part[1]) + (part[2] + part[3]);
}

// ======================= sim kernel (gather only, lean) =======================
// thread = (view, pixel, q). 4 q-lanes cooperatively build depth-invariant
// corner dots; lane q then owns depths d = q + 4k. Guarded slow path if the
// integer corner ever moves.
__global__ void sim_kernel(const float* __restrict__ depth_values) {
    int tid = blockIdx.x * blockDim.x + threadIdx.x;   // NV*NPIX*4
    int q  = tid & 3;
    int vp = tid >> 2;
    int view = 1 + vp / NPIX;
    int pid  = vp % NPIX;
    int b = pid / HWW;
    int p = pid - b * HWW;
    int h = p / WW;
    int w = p - h * WW;

    const float* refp = g_feat_t + ((size_t)(b*VV + 0) * HWW + p) * CC;
    float4 rq = ((const float4*)refp)[q];

    const float* pr = g_proj + ((view-1)*BB + b) * 12;
    float fw = (float)w, fh = (float)h;
    float rx = pr[0]*fw + pr[1]*fh + pr[2];
    float ry = pr[3]*fw + pr[4]*fh + pr[5];
    float rz = pr[6]*fw + pr[7]*fh + pr[8];
    float tx = pr[9], ty = pr[10], tz = pr[11];

    const float* src = g_feat_t + (size_t)(b*VV + view) * HWW * CC;
    const float* dv  = depth_values + (size_t)b * DD * HWW + p;
    float* simout    = g_sim + (size_t)(view-1) * BDHW + (size_t)b * DD * HWW + p;

    float cx0f, cy0f;
    float d00, d10, d01, d11;
    {
        float dep0 = __ldg(dv);
        Coords c = proj_coords(dep0, rx, ry, rz, tx, ty, tz);
        cx0f = c.x0f; cy0f = c.y0f;
        float4 f00 = ((const float4*)(src + ((size_t)(c.iy0*WW + c.ix0)) * CC))[q];
        float4 f10 = ((const float4*)(src + ((size_t)(c.iy0*WW + c.ix1)) * CC))[q];
        float4 f01 = ((const float4*)(src + ((size_t)(c.iy1*WW + c.ix0)) * CC))[q];
        float4 f11 = ((const float4*)(src + ((size_t)(c.iy1*WW + c.ix1)) * CC))[q];
        d00 = fmaf(f00.x, rq.x, fmaf(f00.y, rq.y, fmaf(f00.z, rq.z, f00.w * rq.w)));
        d10 = fmaf(f10.x, rq.x, fmaf(f10.y, rq.y, fmaf(f10.z, rq.z, f10.w * rq.w)));
        d01 = fmaf(f01.x, rq.x, fmaf(f01.y, rq.y, fmaf(f01.z, rq.z, f01.w * rq.w)));
        d11 = fmaf(f11.x, rq.x, fmaf(f11.y, rq.y, fmaf(f11.z, rq.z, f11.w * rq.w)));
        d00 += __shfl_xor_sync(0xffffffffu, d00, 1);
        d10 += __shfl_xor_sync(0xffffffffu, d10, 1);
        d01 += __shfl_xor_sync(0xffffffffu, d01, 1);
        d11 += __shfl_xor_sync(0xffffffffu, d11, 1);
        d00 += __shfl_xor_sync(0xffffffffu, d00, 2);
        d10 += __shfl_xor_sync(0xffffffffu, d10, 2);
        d01 += __shfl_xor_sync(0xffffffffu, d01, 2);
        d11 += __shfl_xor_sync(0xffffffffu, d11, 2);
    }

#pragma unroll 1
    for (int k = 0; k < DD/4; k++) {
        int d = q + 4*k;
        float dep = __ldg(dv + (size_t)d * HWW);
        Coords c = proj_coords(dep, rx, ry, rz, tx, ty, tz);

        if (c.x0f != cx0f || c.y0f != cy0f) {
            cx0f = c.x0f; cy0f = c.y0f;
            d00 = full_dot(src + ((size_t)(c.iy0*WW + c.ix0)) * CC, refp);
            d10 = full_dot(src + ((size_t)(c.iy0*WW + c.ix1)) * CC, refp);
            d01 = full_dot(src + ((size_t)(c.iy1*WW + c.ix0)) * CC, refp);
            d11 = full_dot(src + ((size_t)(c.iy1*WW + c.ix1)) * CC, refp);
        }

        float w00 = (1.f - c.fx) * (1.f - c.fy) * (c.vx0 * c.vy0);
        float w10 = c.fx * (1.f - c.fy) * (c.vx1 * c.vy0);
        float w01 = (1.f - c.fx) * c.fy * (c.vx0 * c.vy1);
        float w11 = c.fx * c.fy * (c.vx1 * c.vy1);

        float sim = fmaf(w00, d00, fmaf(w10, d10, fmaf(w01, d01, w11 * d11))) * 0.0625f;
        simout[(size_t)d * HWW] = sim;
    }
}

// ======================= PWL-MLP + max + sigmoid + combine (fused) =======================
// thread = (pixel, q); lane q owns depths d = q + 4k for both views.
__global__ void mlp_combine_kernel(float* __restrict__ out) {
    __shared__ float s_t[16];
    __shared__ float s_ab[17*16];
    __shared__ float s_w2[9];
    for (int i = threadIdx.x; i < 16; i += blockDim.x)  s_t[i]  = g_pwl_t[i];
    for (int i = threadIdx.x; i < 17*16; i += blockDim.x) s_ab[i] = g_pwl_ab[i];
    for (int i = threadIdx.x; i < 9; i += blockDim.x)   s_w2[i] = g_pwl_w2[i];
    __syncthreads();

    int tid = blockIdx.x * blockDim.x + threadIdx.x;   // NPIX*4
    int q   = tid & 3;
    int pid = tid >> 2;
    int b = pid / HWW;
    int p = pid - b * HWW;

    const float* sp0 = g_sim + (size_t)b * DD * HWW + p;
    const float* sp1 = g_sim + (size_t)BDHW + (size_t)b * DD * HWW + p;

    float s0[DD/4], s1[DD/4];
#pragma unroll
    for (int k = 0; k < DD/4; k++) {
        int d = q + 4*k;
        s0[k] = sp0[(size_t)d * HWW];
        s1[k] = sp1[(size_t)d * HWW];
    }

    // breakpoints into registers
    float th[16];
#pragma unroll
    for (int i = 0; i < 16; i++) th[i] = s_t[i];
    float w2r[8];
#pragma unroll
    for (int j = 0; j < 8; j++) w2r[j] = s_w2[j];
    float fb2 = s_w2[8];

    float omax0 = -3.4e38f, omax1 = -3.4e38f;
#pragma unroll 1
    for (int k = 0; k < DD/4; k++) {
        {
            float s = s0[k];
            int idx = 0;
#pragma unroll
            for (int i = 0; i < 16; i++) idx += (s > th[i]) ? 1 : 0;
            const float* ab = s_ab + idx * 16;
            float ov = fb2;
#pragma unroll
            for (int j = 0; j < 8; j++) {
                float a = fmaf(ab[j], s, ab[8 + j]);
                ov = fmaf(w2r[j], fmaxf(a, 0.f), ov);
            }
            omax0 = fmaxf(omax0, ov);
        }
        {
            float s = s1[k];
            int idx = 0;
#pragma unroll
            for (int i = 0; i < 16; i++) idx += (s > th[i]) ? 1 : 0;
            const float* ab = s_ab + idx * 16;
            float ov = fb2;
#pragma unroll
            for (int j = 0; j < 8; j++) {
                float a = fmaf(ab[j], s, ab[8 + j]);
                ov = fmaf(w2r[j], fmaxf(a, 0.f), ov);
            }
            omax1 = fmaxf(omax1, ov);
        }
    }

    omax0 = fmaxf(omax0, __shfl_xor_sync(0xffffffffu, omax0, 1));
    omax0 = fmaxf(omax0, __shfl_xor_sync(0xffffffffu, omax0, 2));
    omax1 = fmaxf(omax1, __shfl_xor_sync(0xffffffffu, omax1, 1));
    omax1 = fmaxf(omax1, __shfl_xor_sync(0xffffffffu, omax1, 2));

    float vw0 = 1.f / (1.f + expf(-omax0));   // exact sigmoid
    float vw1 = 1.f / (1.f + expf(-omax1));
    if (q == 0) {
        out[OFF_VW + (size_t)b * NV * HWW + p] = vw0;
        out[OFF_VW + (size_t)b * NV * HWW + HWW + p] = vw1;
    }

    float denom = 1e-5f + vw0 + vw1;
    float* so = g_simil + (size_t)b * DD * HWW + p;
#pragma unroll
    for (int k = 0; k < DD/4; k++) {
        int d = q + 4*k;
        so[(size_t)d * HWW] = (s0[k] * vw0 + s1[k] * vw1) / denom;  // exact division
    }
}

// ======================= fused 3x3x3 conv + softmax + argmax + outputs =======================
__global__ void conv_softmax_kernel(const float* __restrict__ depth_values, float* __restrict__ out) {
    __shared__ float s_k[28];
    if (threadIdx.x < 28) s_k[threadIdx.x] = g_reg[threadIdx.x];
    __syncthreads();

    int pid = blockIdx.x * blockDim.x + threadIdx.x;
    if (pid >= NPIX) return;
    int b = pid / HWW;
    int p = pid - b * HWW;
    int h = p / WW;
    int w = p - h * WW;

    float c[DD];
    float bias = s_k[27];
#pragma unroll
    for (int d = 0; d < DD; d++) c[d] = bias;

    bool wl = (w > 0), wr = (w < WW - 1);
#pragma unroll
    for (int dp = 0; dp < DD; dp++) {
        const float* base = g_simil + (size_t)(b*DD + dp) * HWW;
        float n[9];
#pragma unroll
        for (int dy = 0; dy < 3; dy++) {
            int hh = h + dy - 1;
            bool vy = (unsigned)hh < (unsigned)HH;
            const float* rowp = base + hh * WW + w;
            n[dy*3+0] = (vy && wl) ? rowp[-1] : 0.f;
            n[dy*3+1] = vy ? rowp[0] : 0.f;
            n[dy*3+2] = (vy && wr) ? rowp[1] : 0.f;
        }
#pragma unroll
        for (int dz = 0; dz < 3; dz++) {
            int od = dp + 1 - dz;
            if (od < 0 || od >= DD) continue;
            float acc = 0.f;
#pragma unroll
            for (int i = 0; i < 9; i++) acc = fmaf(s_k[dz*9+i], n[i], acc);
            c[od] += acc;
        }
    }

    float m = c[0]; int am = 0;
#pragma unroll
    for (int d = 1; d < DD; d++) if (c[d] > m) { m = c[d]; am = d; }
    float sum = 0.f;
#pragma unroll
    for (int d = 0; d < DD; d++) { float e = __expf(c[d] - m); c[d] = e; sum += e; }
    float inv = __fdividef(1.f, sum);
    float* pp = out + OFF_PROB + (size_t)b * DD * HWW + p;
#pragma unroll
    for (int d = 0; d < DD; d++) pp[(size_t)d * HWW] = c[d] * inv;
    out[OFF_DEPTH + pid] = depth_values[(size_t)b * DD * HWW + (size_t)am * HWW + p];
    out[OFF_CONF + pid] = inv;
}

// ======================= launch =======================
extern "C" void kernel_launch(void* const* d_in, const int* in_sizes, int n_in,
                              void* d_out, int out_size) {
    const float* features     = (const float*)d_in[0];
    const float* proj         = (const float*)d_in[1];
    const float* depth_values = (const float*)d_in[2];
    const float* w0 = (const float*)d_in[3];
    const float* g0 = (const float*)d_in[4];
    const float* b0 = (const float*)d_in[5];
    const float* m0 = (const float*)d_in[6];
    const float* v0 = (const float*)d_in[7];
    const float* w1 = (const float*)d_in[8];
    const float* g1 = (const float*)d_in[9];
    const float* b1 = (const float*)d_in[10];
    const float* m1 = (const float*)d_in[11];
    const float* v1 = (const float*)d_in[12];
    const float* w2 = (const float*)d_in[13];
    const float* b2 = (const float*)d_in[14];
    const float* reg_w = (const float*)d_in[15];
    const float* reg_b = (const float*)d_in[16];
    float* out = (float*)d_out;

    transpose_kernel<<<(BB*VV*HWW + 255) / 256, 256>>>(features);
    prep_kernel<<<1, 32>>>(proj, w0, g0, b0, m0, v0, w1, g1, b1, m1, v1, w2, b2, reg_w, reg_b);
    sim_kernel<<<(NV*NPIX*4) / 128, 128>>>(depth_values);
    mlp_combine_kernel<<<(NPIX*4) / 128, 128>>>(out);
    conv_softmax_kernel<<<(NPIX + 127) / 128, 128>>>(depth_values, out);
}

// round 7
// speedup vs baseline: 3.1220x; 3.1220x over previous
#include <cuda_runtime.h>
#include <math.h>
#include <float.h>

// Fixed problem shapes
#define BB 2
#define VV 3
#define CC 16
#define HH 128
#define WW 160
#define DD 48
#define HWW (HH*WW)            // 20480
#define NPIX (BB*HWW)          // 40960
#define BDHW (BB*DD*HWW)       // 1966080
#define NV (VV-1)              // 2 source views

// Output layout
#define OFF_DEPTH 0
#define OFF_CONF  (NPIX)
#define OFF_PROB  (2*NPIX)
#define OFF_VW    (2*NPIX + BDHW)

// -------- scratch --------
__device__ float g_feat_t[(size_t)BB*VV*HWW*CC];   // [b][v][h][w][c]
__device__ float g_sim[(size_t)NV*BDHW];           // [view][b][d][h][w]
__device__ float g_simil[BDHW];
__device__ float g_proj[NV*BB*12];
__device__ float g_reg[28];
// PWL representation of the pixelwise MLP (function of scalar sim)
__device__ float g_pwl_t[16];        // sorted breakpoints
__device__ float g_pwl_ab[17*16];    // per interval i: alpha[8] then beta[8]
__device__ float g_pwl_w2[9];        // w2[8], b2

// ======================= prep (parallelized) =======================
__device__ void mat4_mul(const double* A, const double* B, double* Cm) {
    for (int r = 0; r < 4; r++)
        for (int c = 0; c < 4; c++) {
            double s = 0.0;
            for (int k = 0; k < 4; k++) s += A[r*4+k] * B[k*4+c];
            Cm[r*4+c] = s;
        }
}

__device__ void compose_proj(const float* p, double* out) {
    const float* E = p;
    const float* K = p + 16;
    for (int i = 0; i < 16; i++) out[i] = (double)E[i];
    for (int r = 0; r < 3; r++)
        for (int c = 0; c < 4; c++) {
            double s = 0.0;
            for (int k = 0; k < 3; k++) s += (double)K[r*4+k] * (double)E[k*4+c];
            out[r*4+c] = s;
        }
}

__device__ void inv4(const double* A, double* out) {
    double M[4][8];
    for (int i = 0; i < 4; i++)
        for (int j = 0; j < 4; j++) { M[i][j] = A[i*4+j]; M[i][4+j] = (i == j) ? 1.0 : 0.0; }
    for (int col = 0; col < 4; col++) {
        int piv = col;
        for (int r = col + 1; r < 4; r++)
            if (fabs(M[r][col]) > fabs(M[piv][col])) piv = r;
        if (piv != col)
            for (int j = 0; j < 8; j++) { double t = M[col][j]; M[col][j] = M[piv][j]; M[piv][j] = t; }
        double pv = M[col][col];
        for (int j = 0; j < 8; j++) M[col][j] /= pv;
        for (int r = 0; r < 4; r++) {
            if (r == col) continue;
            double f = M[r][col];
            for (int j = 0; j < 8; j++) M[r][j] -= f * M[col][j];
        }
    }
    for (int i = 0; i < 4; i++)
        for (int j = 0; j < 4; j++) out[i*4+j] = M[i][4+j];
}

__global__ void prep_kernel(const float* proj,
                            const float* w0, const float* g0, const float* b0,
                            const float* m0, const float* v0,
                            const float* w1, const float* g1, const float* b1,
                            const float* m1, const float* v1,
                            const float* w2, const float* b2,
                            const float* reg_w, const float* reg_b) {
    __shared__ float  sh_fw0[16], sh_fc0[16];
    __shared__ float  sh_fw1[8][16], sh_fc1[8];
    __shared__ int    sh_pos[16];

    int tid = threadIdx.x;

    if (tid == 0) {
        // matrices
        for (int b = 0; b < BB; b++) {
            double refc[16], refi[16];
            compose_proj(proj + (size_t)(b*VV + 0)*2*16, refc);
            inv4(refc, refi);
            for (int v = 1; v < VV; v++) {
                double srcc[16], P[16];
                compose_proj(proj + (size_t)(b*VV + v)*2*16, srcc);
                mat4_mul(srcc, refi, P);
                float* dst = g_proj + ((v-1)*BB + b)*12;
                for (int r = 0; r < 3; r++)
                    for (int c = 0; c < 3; c++) dst[r*3+c] = (float)P[r*4+c];
                dst[9]  = (float)P[0*4+3];
                dst[10] = (float)P[1*4+3];
                dst[11] = (float)P[2*4+3];
            }
        }
        // fold BN
        for (int o = 0; o < 16; o++) {
            double s = (double)g0[o] / sqrt((double)v0[o] + 1e-5);
            sh_fw0[o] = (float)((double)w0[o] * s);
            sh_fc0[o] = (float)((double)b0[o] - (double)m0[o] * s);
        }
        for (int j = 0; j < 8; j++) {
            double s = (double)g1[j] / sqrt((double)v1[j] + 1e-5);
            for (int o = 0; o < 16; o++)
                sh_fw1[j][o] = (float)((double)w1[j*16+o] * s);
            sh_fc1[j] = (float)((double)b1[j] - (double)m1[j] * s);
            g_pwl_w2[j] = w2[j];
        }
        g_pwl_w2[8] = b2[0];
        for (int k = 0; k < 27; k++) g_reg[k] = reg_w[k];
        g_reg[27] = reg_b[0];

        // breakpoints + sort (16 elems, cheap)
        double t[16]; int ord[16];
        for (int o = 0; o < 16; o++) {
            if (sh_fw0[o] != 0.f) t[o] = -(double)sh_fc0[o] / (double)sh_fw0[o];
            else                  t[o] = DBL_MAX;
            ord[o] = o;
        }
        for (int i = 1; i < 16; i++) {
            int k = ord[i]; double tv = t[k]; int j = i - 1;
            while (j >= 0 && t[ord[j]] > tv) { ord[j+1] = ord[j]; j--; }
            ord[j+1] = k;
        }
        for (int k = 0; k < 16; k++) {
            double tv = t[ord[k]];
            g_pwl_t[k] = (tv >= DBL_MAX) ? FLT_MAX : (float)tv;
            sh_pos[ord[k]] = k;
        }
    }
    __syncthreads();

    // parallel PWL table build: one thread per (interval i, unit j)
    if (tid < 17*8) {
        int i = tid / 8;
        int j = tid % 8;
        double alpha = 0.0, beta = (double)sh_fc1[j];
        for (int o = 0; o < 16; o++) {
            bool active;
            float fw0o = sh_fw0[o];
            if (fw0o > 0.f)      active = (sh_pos[o] < i);
            else if (fw0o < 0.f) active = (sh_pos[o] >= i);
            else                 active = (sh_fc0[o] > 0.f);
            if (active) {
                alpha += (double)sh_fw1[j][o] * (double)fw0o;
                beta  += (double)sh_fw1[j][o] * (double)sh_fc0[o];
            }
        }
        g_pwl_ab[i*16 + j]     = (float)alpha;
        g_pwl_ab[i*16 + 8 + j] = (float)beta;
    }
}

// ======================= feature transpose to [b][v][h][w][c] =======================
__global__ void transpose_kernel(const float* __restrict__ feat) {
    int idx = blockIdx.x * blockDim.x + threadIdx.x;
    if (idx >= BB*VV*HWW) return;
    int p  = idx % HWW;
    int bv = idx / HWW;
    const float* src = feat + (size_t)bv * CC * HWW + p;
    float v[CC];
#pragma unroll
    for (int c = 0; c < CC; c++) v[c] = src[(size_t)c * HWW];
    float4* dst = (float4*)(g_feat_t + ((size_t)bv * HWW + p) * CC);
    dst[0] = make_float4(v[0],  v[1],  v[2],  v[3]);
    dst[1] = make_float4(v[4],  v[5],  v[6],  v[7]);
    dst[2] = make_float4(v[8],  v[9],  v[10], v[11]);
    dst[3] = make_float4(v[12], v[13], v[14], v[15]);
}

// helper: coords for one depth
struct Coords {
    float x0f, y0f, fx, fy;
    int ix0, ix1, iy0, iy1;
    float vx0, vx1, vy0, vy1;
};
__device__ __forceinline__ Coords proj_coords(float dep, float rx, float ry, float rz,
                                              float tx, float ty, float tz) {
    Coords c;
    float X = fmaf(rx, dep, tx);
    float Y = fmaf(ry, dep, ty);
    float Z = fmaf(rz, dep, tz);
    float px = X / Z;            // exact IEEE division (argmax-sensitive)
    float py = Y / Z;
    c.x0f = floorf(px); c.y0f = floorf(py);
    c.fx = px - c.x0f;  c.fy = py - c.y0f;
    c.vx0 = (c.x0f >= 0.f       && c.x0f       <= (float)(WW-1)) ? 1.f : 0.f;
    c.vx1 = (c.x0f + 1.f >= 0.f && c.x0f + 1.f <= (float)(WW-1)) ? 1.f : 0.f;
    c.vy0 = (c.y0f >= 0.f       && c.y0f       <= (float)(HH-1)) ? 1.f : 0.f;
    c.vy1 = (c.y0f + 1.f >= 0.f && c.y0f + 1.f <= (float)(HH-1)) ? 1.f : 0.f;
    c.ix0 = (int)fminf(fmaxf(c.x0f,       0.f), (float)(WW-1));
    c.ix1 = (int)fminf(fmaxf(c.x0f + 1.f, 0.f), (float)(WW-1));
    c.iy0 = (int)fminf(fmaxf(c.y0f,       0.f), (float)(HH-1));
    c.iy1 = (int)fminf(fmaxf(c.y0f + 1.f, 0.f), (float)(HH-1));
    return c;
}

// full 16-ch dot grouped as ((q0+q1)+(q2+q3)) -- matches butterfly order
__device__ __forceinline__ float full_dot(const float* fp, const float* rp) {
    float part[4];
#pragma unroll
    for (int qq = 0; qq < 4; qq++) {
        float4 f = ((const float4*)fp)[qq];
        float4 r = ((const float4*)rp)[qq];
        part[qq] = fmaf(f.x, r.x, fmaf(f.y, r.y, fmaf(f.z, r.z, f.w * r.w)));
    }
    return (part[0] + part[1]) + (part[2] + part[3]);
}

__device__ __forceinline__ float quarter_dot(const float* fp, int q, float4 rq) {
    float4 f = ((const float4*)fp)[q];
    return fmaf(f.x, rq.x, fmaf(f.y, rq.y, fmaf(f.z, rq.z, f.w * rq.w)));
}

// PWL MLP eval
__device__ __forceinline__ float pwl_eval(float s, const float* s_t, const float* s_ab,
                                          const float* w2r, float fb2) {
    int idx = 0;
#pragma unroll
    for (int i = 0; i < 16; i++) idx += (s > s_t[i]) ? 1 : 0;
    const float* ab = s_ab + idx * 16;
    float ov = fb2;
#pragma unroll
    for (int j = 0; j < 8; j++) {
        float a = fmaf(ab[j], s, ab[8 + j]);
        ov = fmaf(w2r[j], fmaxf(a, 0.f), ov);
    }
    return ov;
}

// ======================= fused: gather(2 views) + PWL-MLP + sigmoid + combine =======================
// thread = (pixel, q). Each thread handles BOTH views for depths d = q + 4k.
// Loop 1: sims + PWL + omax (sims stored to g_sim). Loop 2 (after sigmoids):
// re-read own sims (L2-hot) and write combined similarity.
__global__ void main_kernel(const float* __restrict__ depth_values,
                            float* __restrict__ out) {
    __shared__ float s_t[16];
    __shared__ float s_ab[17*16];
    __shared__ float s_w2[9];
    for (int i = threadIdx.x; i < 16; i += blockDim.x)    s_t[i]  = g_pwl_t[i];
    for (int i = threadIdx.x; i < 17*16; i += blockDim.x) s_ab[i] = g_pwl_ab[i];
    for (int i = threadIdx.x; i < 9; i += blockDim.x)     s_w2[i] = g_pwl_w2[i];
    __syncthreads();

    int tid = blockIdx.x * blockDim.x + threadIdx.x;   // NPIX*4
    int q   = tid & 3;
    int pid = tid >> 2;
    int b = pid / HWW;
    int p = pid - b * HWW;
    int h = p / WW;
    int w = p - h * WW;

    const float* refp = g_feat_t + ((size_t)(b*VV + 0) * HWW + p) * CC;
    float4 rq = ((const float4*)refp)[q];

    // projection rows for both source views
    float rx[2], ry[2], rz[2], tx[2], ty[2], tz[2];
#pragma unroll
    for (int v = 0; v < 2; v++) {
        const float* pr = g_proj + (v*BB + b) * 12;
        float fw = (float)w, fh = (float)h;
        rx[v] = pr[0]*fw + pr[1]*fh + pr[2];
        ry[v] = pr[3]*fw + pr[4]*fh + pr[5];
        rz[v] = pr[6]*fw + pr[7]*fh + pr[8];
        tx[v] = pr[9]; ty[v] = pr[10]; tz[v] = pr[11];
    }
    const float* src0 = g_feat_t + (size_t)(b*VV + 1) * HWW * CC;
    const float* src1 = g_feat_t + (size_t)(b*VV + 2) * HWW * CC;
    const float* dv   = depth_values + (size_t)b * DD * HWW + p;
    float* sim0out    = g_sim + (size_t)b * DD * HWW + p;
    float* sim1out    = g_sim + (size_t)BDHW + (size_t)b * DD * HWW + p;

    float w2r[8];
#pragma unroll
    for (int j = 0; j < 8; j++) w2r[j] = s_w2[j];
    float fb2 = s_w2[8];

    // ---- setup: cooperative corner dots at depth 0 for both views ----
    float cx0f0, cy0f0, cx0f1, cy0f1;
    float dA00, dA10, dA01, dA11;   // view 0 dots
    float dB00, dB10, dB01, dB11;   // view 1 dots
    {
        float dep0 = __ldg(dv);
        Coords c0 = proj_coords(dep0, rx[0], ry[0], rz[0], tx[0], ty[0], tz[0]);
        Coords c1 = proj_coords(dep0, rx[1], ry[1], rz[1], tx[1], ty[1], tz[1]);
        cx0f0 = c0.x0f; cy0f0 = c0.y0f;
        cx0f1 = c1.x0f; cy0f1 = c1.y0f;
        dA00 = quarter_dot(src0 + ((size_t)(c0.iy0*WW + c0.ix0)) * CC, q, rq);
        dA10 = quarter_dot(src0 + ((size_t)(c0.iy0*WW + c0.ix1)) * CC, q, rq);
        dA01 = quarter_dot(src0 + ((size_t)(c0.iy1*WW + c0.ix0)) * CC, q, rq);
        dA11 = quarter_dot(src0 + ((size_t)(c0.iy1*WW + c0.ix1)) * CC, q, rq);
        dB00 = quarter_dot(src1 + ((size_t)(c1.iy0*WW + c1.ix0)) * CC, q, rq);
        dB10 = quarter_dot(src1 + ((size_t)(c1.iy0*WW + c1.ix1)) * CC, q, rq);
        dB01 = quarter_dot(src1 + ((size_t)(c1.iy1*WW + c1.ix0)) * CC, q, rq);
        dB11 = quarter_dot(src1 + ((size_t)(c1.iy1*WW + c1.ix1)) * CC, q, rq);
#pragma unroll
        for (int m = 1; m <= 2; m <<= 1) {
            dA00 += __shfl_xor_sync(0xffffffffu, dA00, m);
            dA10 += __shfl_xor_sync(0xffffffffu, dA10, m);
            dA01 += __shfl_xor_sync(0xffffffffu, dA01, m);
            dA11 += __shfl_xor_sync(0xffffffffu, dA11, m);
            dB00 += __shfl_xor_sync(0xffffffffu, dB00, m);
            dB10 += __shfl_xor_sync(0xffffffffu, dB10, m);
            dB01 += __shfl_xor_sync(0xffffffffu, dB01, m);
            dB11 += __shfl_xor_sync(0xffffffffu, dB11, m);
        }
    }

    float omax0 = -3.4e38f, omax1 = -3.4e38f;

#pragma unroll 1
    for (int k = 0; k < DD/4; k++) {
        int d = q + 4*k;
        float dep = __ldg(dv + (size_t)d * HWW);

        // view 0
        {
            Coords c = proj_coords(dep, rx[0], ry[0], rz[0], tx[0], ty[0], tz[0]);
            if (c.x0f != cx0f0 || c.y0f != cy0f0) {
                cx0f0 = c.x0f; cy0f0 = c.y0f;
                dA00 = full_dot(src0 + ((size_t)(c.iy0*WW + c.ix0)) * CC, refp);
                dA10 = full_dot(src0 + ((size_t)(c.iy0*WW + c.ix1)) * CC, refp);
                dA01 = full_dot(src0 + ((size_t)(c.iy1*WW + c.ix0)) * CC, refp);
                dA11 = full_dot(src0 + ((size_t)(c.iy1*WW + c.ix1)) * CC, refp);
            }
            float w00 = (1.f - c.fx) * (1.f - c.fy) * (c.vx0 * c.vy0);
            float w10 = c.fx * (1.f - c.fy) * (c.vx1 * c.vy0);
            float w01 = (1.f - c.fx) * c.fy * (c.vx0 * c.vy1);
            float w11 = c.fx * c.fy * (c.vx1 * c.vy1);
            float sim = fmaf(w00, dA00, fmaf(w10, dA10, fmaf(w01, dA01, w11 * dA11))) * 0.0625f;
            sim0out[(size_t)d * HWW] = sim;
            omax0 = fmaxf(omax0, pwl_eval(sim, s_t, s_ab, w2r, fb2));
        }
        // view 1
        {
            Coords c = proj_coords(dep, rx[1], ry[1], rz[1], tx[1], ty[1], tz[1]);
            if (c.x0f != cx0f1 || c.y0f != cy0f1) {
                cx0f1 = c.x0f; cy0f1 = c.y0f;
                dB00 = full_dot(src1 + ((size_t)(c.iy0*WW + c.ix0)) * CC, refp);
                dB10 = full_dot(src1 + ((size_t)(c.iy0*WW + c.ix1)) * CC, refp);
                dB01 = full_dot(src1 + ((size_t)(c.iy1*WW + c.ix0)) * CC, refp);
                dB11 = full_dot(src1 + ((size_t)(c.iy1*WW + c.ix1)) * CC, refp);
            }
            float w00 = (1.f - c.fx) * (1.f - c.fy) * (c.vx0 * c.vy0);
            float w10 = c.fx * (1.f - c.fy) * (c.vx1 * c.vy0);
            float w01 = (1.f - c.fx) * c.fy * (c.vx0 * c.vy1);
            float w11 = c.fx * c.fy * (c.vx1 * c.vy1);
            float sim = fmaf(w00, dB00, fmaf(w10, dB10, fmaf(w01, dB01, w11 * dB11))) * 0.0625f;
            sim1out[(size_t)d * HWW] = sim;
            omax1 = fmaxf(omax1, pwl_eval(sim, s_t, s_ab, w2r, fb2));
        }
    }

    // max over the 4 q-lanes
    omax0 = fmaxf(omax0, __shfl_xor_sync(0xffffffffu, omax0, 1));
    omax0 = fmaxf(omax0, __shfl_xor_sync(0xffffffffu, omax0, 2));
    omax1 = fmaxf(omax1, __shfl_xor_sync(0xffffffffu, omax1, 1));
    omax1 = fmaxf(omax1, __shfl_xor_sync(0xffffffffu, omax1, 2));

    float vw0 = 1.f / (1.f + expf(-omax0));   // exact sigmoid
    float vw1 = 1.f / (1.f + expf(-omax1));
    if (q == 0) {
        out[OFF_VW + (size_t)b * NV * HWW + p] = vw0;
        out[OFF_VW + (size_t)b * NV * HWW + HWW + p] = vw1;
    }

    // combine (re-read own sims, L2-hot; same-thread visibility)
    float denom = 1e-5f + vw0 + vw1;
    float* so = g_simil + (size_t)b * DD * HWW + p;
#pragma unroll 1
    for (int k = 0; k < DD/4; k++) {
        int d = q + 4*k;
        float sa = sim0out[(size_t)d * HWW];
        float sb = sim1out[(size_t)d * HWW];
        so[(size_t)d * HWW] = (sa * vw0 + sb * vw1) / denom;   // exact division
    }
}

// ======================= fused 3x3x3 conv + softmax + argmax + outputs =======================
__global__ void conv_softmax_kernel(const float* __restrict__ depth_values, float* __restrict__ out) {
    __shared__ float s_k[28];
    if (threadIdx.x < 28) s_k[threadIdx.x] = g_reg[threadIdx.x];
    __syncthreads();

    int pid = blockIdx.x * blockDim.x + threadIdx.x;
    if (pid >= NPIX) return;
    int b = pid / HWW;
    int p = pid - b * HWW;
    int h = p / WW;
    int w = p - h * WW;

    float c[DD];
    float bias = s_k[27];
#pragma unroll
    for (int d = 0; d < DD; d++) c[d] = bias;

    bool wl = (w > 0), wr = (w < WW - 1);
#pragma unroll
    for (int dp = 0; dp < DD; dp++) {
        const float* base = g_simil + (size_t)(b*DD + dp) * HWW;
        float n[9];
#pragma unroll
        for (int dy = 0; dy < 3; dy++) {
            int hh = h + dy - 1;
            bool vy = (unsigned)hh < (unsigned)HH;
            const float* rowp = base + hh * WW + w;
            n[dy*3+0] = (vy && wl) ? rowp[-1] : 0.f;
            n[dy*3+1] = vy ? rowp[0] : 0.f;
            n[dy*3+2] = (vy && wr) ? rowp[1] : 0.f;
        }
#pragma unroll
        for (int dz = 0; dz < 3; dz++) {
            int od = dp + 1 - dz;
            if (od < 0 || od >= DD) continue;
            float acc = 0.f;
#pragma unroll
            for (int i = 0; i < 9; i++) acc = fmaf(s_k[dz*9+i], n[i], acc);
            c[od] += acc;
        }
    }

    float m = c[0]; int am = 0;
#pragma unroll
    for (int d = 1; d < DD; d++) if (c[d] > m) { m = c[d]; am = d; }
    float sum = 0.f;
#pragma unroll
    for (int d = 0; d < DD; d++) { float e = __expf(c[d] - m); c[d] = e; sum += e; }
    float inv = __fdividef(1.f, sum);
    float* pp = out + OFF_PROB + (size_t)b * DD * HWW + p;
#pragma unroll
    for (int d = 0; d < DD; d++) pp[(size_t)d * HWW] = c[d] * inv;
    out[OFF_DEPTH + pid] = depth_values[(size_t)b * DD * HWW + (size_t)am * HWW + p];
    out[OFF_CONF + pid] = inv;
}

// ======================= launch =======================
extern "C" void kernel_launch(void* const* d_in, const int* in_sizes, int n_in,
                              void* d_out, int out_size) {
    const float* features     = (const float*)d_in[0];
    const float* proj         = (const float*)d_in[1];
    const float* depth_values = (const float*)d_in[2];
    const float* w0 = (const float*)d_in[3];
    const float* g0 = (const float*)d_in[4];
    const float* b0 = (const float*)d_in[5];
    const float* m0 = (const float*)d_in[6];
    const float* v0 = (const float*)d_in[7];
    const float* w1 = (const float*)d_in[8];
    const float* g1 = (const float*)d_in[9];
    const float* b1 = (const float*)d_in[10];
    const float* m1 = (const float*)d_in[11];
    const float* v1 = (const float*)d_in[12];
    const float* w2 = (const float*)d_in[13];
    const float* b2 = (const float*)d_in[14];
    const float* reg_w = (const float*)d_in[15];
    const float* reg_b = (const float*)d_in[16];
    float* out = (float*)d_out;

    transpose_kernel<<<(BB*VV*HWW + 255) / 256, 256>>>(features);
    prep_kernel<<<1, 256>>>(proj, w0, g0, b0, m0, v0, w1, g1, b1, m1, v1, w2, b2, reg_w, reg_b);
    main_kernel<<<(NPIX*4) / 128, 128>>>(depth_values, out);
    conv_softmax_kernel<<<(NPIX + 127) / 128, 128>>>(depth_values, out);
}

// round 8
// speedup vs baseline: 3.4692x; 1.1112x over previous
#include <cuda_runtime.h>
#include <math.h>
#include <float.h>

// Fixed problem shapes
#define BB 2
#define VV 3
#define CC 16
#define HH 128
#define WW 160
#define DD 48
#define HWW (HH*WW)            // 20480
#define NPIX (BB*HWW)          // 40960
#define BDHW (BB*DD*HWW)       // 1966080
#define NV (VV-1)              // 2 source views

// Output layout
#define OFF_DEPTH 0
#define OFF_CONF  (NPIX)
#define OFF_PROB  (2*NPIX)
#define OFF_VW    (2*NPIX + BDHW)

// -------- scratch --------
__device__ float g_feat_t[(size_t)BB*VV*HWW*CC];   // [b][v][h][w][c]
__device__ float g_sim[(size_t)NV*BDHW];           // [view][b][d][h][w]
__device__ float g_simil[BDHW];
__device__ float g_proj[NV*BB*12];
__device__ float g_reg[28];
// PWL representation of the pixelwise MLP (function of scalar sim)
__device__ float g_pwl_t[16];                     // sorted breakpoints
__device__ __align__(16) float g_pwl_ab[17*16];   // per interval i: alpha[8] then beta[8]
__device__ float g_pwl_w2[9];                     // w2[8], b2

// ======================= prep (parallelized) =======================
__device__ void mat4_mul(const double* A, const double* B, double* Cm) {
    for (int r = 0; r < 4; r++)
        for (int c = 0; c < 4; c++) {
            double s = 0.0;
            for (int k = 0; k < 4; k++) s += A[r*4+k] * B[k*4+c];
            Cm[r*4+c] = s;
        }
}

__device__ void compose_proj(const float* p, double* out) {
    const float* E = p;
    const float* K = p + 16;
    for (int i = 0; i < 16; i++) out[i] = (double)E[i];
    for (int r = 0; r < 3; r++)
        for (int c = 0; c < 4; c++) {
            double s = 0.0;
            for (int k = 0; k < 3; k++) s += (double)K[r*4+k] * (double)E[k*4+c];
            out[r*4+c] = s;
        }
}

__device__ void inv4(const double* A, double* out) {
    double M[4][8];
    for (int i = 0; i < 4; i++)
        for (int j = 0; j < 4; j++) { M[i][j] = A[i*4+j]; M[i][4+j] = (i == j) ? 1.0 : 0.0; }
    for (int col = 0; col < 4; col++) {
        int piv = col;
        for (int r = col + 1; r < 4; r++)
            if (fabs(M[r][col]) > fabs(M[piv][col])) piv = r;
        if (piv != col)
            for (int j = 0; j < 8; j++) { double t = M[col][j]; M[col][j] = M[piv][j]; M[piv][j] = t; }
        double pv = M[col][col];
        for (int j = 0; j < 8; j++) M[col][j] /= pv;
        for (int r = 0; r < 4; r++) {
            if (r == col) continue;
            double f = M[r][col];
            for (int j = 0; j < 8; j++) M[r][j] -= f * M[col][j];
        }
    }
    for (int i = 0; i < 4; i++)
        for (int j = 0; j < 4; j++) out[i*4+j] = M[i][4+j];
}

__global__ void prep_kernel(const float* proj,
                            const float* w0, const float* g0, const float* b0,
                            const float* m0, const float* v0,
                            const float* w1, const float* g1, const float* b1,
                            const float* m1, const float* v1,
                            const float* w2, const float* b2,
                            const float* reg_w, const float* reg_b) {
    __shared__ float  sh_fw0[16], sh_fc0[16];
    __shared__ float  sh_fw1[8][16], sh_fc1[8];
    __shared__ int    sh_pos[16];

    int tid = threadIdx.x;

    // ---- matrices: 4 threads, one per (b, view) ----
    if (tid < NV*BB) {
        int b = tid % BB;
        int v = 1 + tid / BB;
        double refc[16], refi[16], srcc[16], P[16];
        compose_proj(proj + (size_t)(b*VV + 0)*2*16, refc);
        inv4(refc, refi);
        compose_proj(proj + (size_t)(b*VV + v)*2*16, srcc);
        mat4_mul(srcc, refi, P);
        float* dst = g_proj + ((v-1)*BB + b)*12;
        for (int r = 0; r < 3; r++)
            for (int c = 0; c < 3; c++) dst[r*3+c] = (float)P[r*4+c];
        dst[9]  = (float)P[0*4+3];
        dst[10] = (float)P[1*4+3];
        dst[11] = (float)P[2*4+3];
    }

    if (tid == 0) {
        // fold BN
        for (int o = 0; o < 16; o++) {
            double s = (double)g0[o] / sqrt((double)v0[o] + 1e-5);
            sh_fw0[o] = (float)((double)w0[o] * s);
            sh_fc0[o] = (float)((double)b0[o] - (double)m0[o] * s);
        }
        for (int j = 0; j < 8; j++) {
            double s = (double)g1[j] / sqrt((double)v1[j] + 1e-5);
            for (int o = 0; o < 16; o++)
                sh_fw1[j][o] = (float)((double)w1[j*16+o] * s);
            sh_fc1[j] = (float)((double)b1[j] - (double)m1[j] * s);
            g_pwl_w2[j] = w2[j];
        }
        g_pwl_w2[8] = b2[0];
        for (int k = 0; k < 27; k++) g_reg[k] = reg_w[k];
        g_reg[27] = reg_b[0];

        // breakpoints + sort
        double t[16]; int ord[16];
        for (int o = 0; o < 16; o++) {
            if (sh_fw0[o] != 0.f) t[o] = -(double)sh_fc0[o] / (double)sh_fw0[o];
            else                  t[o] = DBL_MAX;
            ord[o] = o;
        }
        for (int i = 1; i < 16; i++) {
            int k = ord[i]; double tv = t[k]; int j = i - 1;
            while (j >= 0 && t[ord[j]] > tv) { ord[j+1] = ord[j]; j--; }
            ord[j+1] = k;
        }
        for (int k = 0; k < 16; k++) {
            double tv = t[ord[k]];
            g_pwl_t[k] = (tv >= DBL_MAX) ? FLT_MAX : (float)tv;
            sh_pos[ord[k]] = k;
        }
    }
    __syncthreads();

    // parallel PWL table build: one thread per (interval i, unit j)
    if (tid < 17*8) {
        int i = tid / 8;
        int j = tid % 8;
        double alpha = 0.0, beta = (double)sh_fc1[j];
        for (int o = 0; o < 16; o++) {
            bool active;
            float fw0o = sh_fw0[o];
            if (fw0o > 0.f)      active = (sh_pos[o] < i);
            else if (fw0o < 0.f) active = (sh_pos[o] >= i);
            else                 active = (sh_fc0[o] > 0.f);
            if (active) {
                alpha += (double)sh_fw1[j][o] * (double)fw0o;
                beta  += (double)sh_fw1[j][o] * (double)sh_fc0[o];
            }
        }
        g_pwl_ab[i*16 + j]     = (float)alpha;
        g_pwl_ab[i*16 + 8 + j] = (float)beta;
    }
}

// ======================= feature transpose to [b][v][h][w][c] =======================
// launched twice over half-ranges (keeps main_kernel as the 4th launch for ncu)
__global__ void transpose_kernel(const float* __restrict__ feat, int off) {
    int idx = off + blockIdx.x * blockDim.x + threadIdx.x;
    if (idx >= BB*VV*HWW) return;
    int p  = idx % HWW;
    int bv = idx / HWW;
    const float* src = feat + (size_t)bv * CC * HWW + p;
    float v[CC];
#pragma unroll
    for (int c = 0; c < CC; c++) v[c] = src[(size_t)c * HWW];
    float4* dst = (float4*)(g_feat_t + ((size_t)bv * HWW + p) * CC);
    dst[0] = make_float4(v[0],  v[1],  v[2],  v[3]);
    dst[1] = make_float4(v[4],  v[5],  v[6],  v[7]);
    dst[2] = make_float4(v[8],  v[9],  v[10], v[11]);
    dst[3] = make_float4(v[12], v[13], v[14], v[15]);
}

// helper: coords for one depth (indices/valid via integer ops)
struct Coords {
    float fx, fy;
    int jx0, jy0;                // unclamped floor (saturating) -- corner identity
    int ix0, ix1, iy0, iy1;      // clamped indices
    float m00, m10, m01, m11;    // validity masks
};
__device__ __forceinline__ Coords proj_coords(float dep, float rx, float ry, float rz,
                                              float tx, float ty, float tz) {
    Coords c;
    float X = fmaf(rx, dep, tx);
    float Y = fmaf(ry, dep, ty);
    float Z = fmaf(rz, dep, tz);
    float px = X / Z;            // exact IEEE division (argmax-sensitive)
    float py = Y / Z;
    float x0f = floorf(px), y0f = floorf(py);
    c.fx = px - x0f; c.fy = py - y0f;
    c.jx0 = __float2int_rd(px);  // saturating floor-convert
    c.jy0 = __float2int_rd(py);
    bool bx0 = (c.jx0 >= 0)  && (c.jx0 <  WW);
    bool bx1 = (c.jx0 >= -1) && (c.jx0 <  WW-1);
    bool by0 = (c.jy0 >= 0)  && (c.jy0 <  HH);
    bool by1 = (c.jy0 >= -1) && (c.jy0 <  HH-1);
    c.m00 = (bx0 && by0) ? 1.f : 0.f;
    c.m10 = (bx1 && by0) ? 1.f : 0.f;
    c.m01 = (bx0 && by1) ? 1.f : 0.f;
    c.m11 = (bx1 && by1) ? 1.f : 0.f;
    c.ix0 = min(max(c.jx0,     0), WW-1);
    c.ix1 = min(max(c.jx0 + 1, 0), WW-1);
    c.iy0 = min(max(c.jy0,     0), HH-1);
    c.iy1 = min(max(c.jy0 + 1, 0), HH-1);
    return c;
}

// full 16-ch dot grouped as ((q0+q1)+(q2+q3)) -- matches butterfly order
__device__ __forceinline__ float full_dot(const float* fp, const float* rp) {
    float part[4];
#pragma unroll
    for (int qq = 0; qq < 4; qq++) {
        float4 f = ((const float4*)fp)[qq];
        float4 r = ((const float4*)rp)[qq];
        part[qq] = fmaf(f.x, r.x, fmaf(f.y, r.y, fmaf(f.z, r.z, f.w * r.w)));
    }
    return (part[0] + part[1]) + (part[2] + part[3]);
}

__device__ __forceinline__ float quarter_dot(const float* fp, int q, float4 rq) {
    float4 f = ((const float4*)fp)[q];
    return fmaf(f.x, rq.x, fmaf(f.y, rq.y, fmaf(f.z, rq.z, f.w * rq.w)));
}

// PWL MLP eval -- vectorized table loads (ab rows are 64B aligned)
__device__ __forceinline__ float pwl_eval(float s, const float* s_t, const float* s_ab,
                                          const float* w2r, float fb2) {
    int idx = 0;
#pragma unroll
    for (int i = 0; i < 16; i++) idx += (s > s_t[i]) ? 1 : 0;
    const float4* abv = (const float4*)(s_ab + idx * 16);
    float4 A0 = abv[0], A1 = abv[1], B0 = abv[2], B1 = abv[3];
    float ov = fb2;
    ov = fmaf(w2r[0], fmaxf(fmaf(A0.x, s, B0.x), 0.f), ov);
    ov = fmaf(w2r[1], fmaxf(fmaf(A0.y, s, B0.y), 0.f), ov);
    ov = fmaf(w2r[2], fmaxf(fmaf(A0.z, s, B0.z), 0.f), ov);
    ov = fmaf(w2r[3], fmaxf(fmaf(A0.w, s, B0.w), 0.f), ov);
    ov = fmaf(w2r[4], fmaxf(fmaf(A1.x, s, B1.x), 0.f), ov);
    ov = fmaf(w2r[5], fmaxf(fmaf(A1.y, s, B1.y), 0.f), ov);
    ov = fmaf(w2r[6], fmaxf(fmaf(A1.z, s, B1.z), 0.f), ov);
    ov = fmaf(w2r[7], fmaxf(fmaf(A1.w, s, B1.w), 0.f), ov);
    return ov;
}

// ======================= fused: gather(2 views) + PWL-MLP + sigmoid + combine =======================
__global__ void main_kernel(const float* __restrict__ depth_values,
                            float* __restrict__ out) {
    __shared__ float s_t[16];
    __shared__ __align__(16) float s_ab[17*16];
    __shared__ float s_w2[9];
    for (int i = threadIdx.x; i < 16; i += blockDim.x)    s_t[i]  = g_pwl_t[i];
    for (int i = threadIdx.x; i < 17*16; i += blockDim.x) s_ab[i] = g_pwl_ab[i];
    for (int i = threadIdx.x; i < 9; i += blockDim.x)     s_w2[i] = g_pwl_w2[i];
    __syncthreads();

    int tid = blockIdx.x * blockDim.x + threadIdx.x;   // NPIX*4
    int q   = tid & 3;
    int pid = tid >> 2;
    int b = pid / HWW;
    int p = pid - b * HWW;
    int h = p / WW;
    int w = p - h * WW;

    const float* refp = g_feat_t + ((size_t)(b*VV + 0) * HWW + p) * CC;
    float4 rq = ((const float4*)refp)[q];

    float rx[2], ry[2], rz[2], tx[2], ty[2], tz[2];
#pragma unroll
    for (int v = 0; v < 2; v++) {
        const float* pr = g_proj + (v*BB + b) * 12;
        float fw = (float)w, fh = (float)h;
        rx[v] = pr[0]*fw + pr[1]*fh + pr[2];
        ry[v] = pr[3]*fw + pr[4]*fh + pr[5];
        rz[v] = pr[6]*fw + pr[7]*fh + pr[8];
        tx[v] = pr[9]; ty[v] = pr[10]; tz[v] = pr[11];
    }
    const float* src0 = g_feat_t + (size_t)(b*VV + 1) * HWW * CC;
    const float* src1 = g_feat_t + (size_t)(b*VV + 2) * HWW * CC;
    const float* dv   = depth_values + (size_t)b * DD * HWW + p;
    float* sim0out    = g_sim + (size_t)b * DD * HWW + p;
    float* sim1out    = g_sim + (size_t)BDHW + (size_t)b * DD * HWW + p;

    float w2r[8];
#pragma unroll
    for (int j = 0; j < 8; j++) w2r[j] = s_w2[j];
    float fb2 = s_w2[8];

    // ---- setup: cooperative corner dots at depth 0 for both views ----
    int cjx0, cjy0, cjx1, cjy1;
    float dA00, dA10, dA01, dA11;
    float dB00, dB10, dB01, dB11;
    {
        float dep0 = __ldg(dv);
        Coords c0 = proj_coords(dep0, rx[0], ry[0], rz[0], tx[0], ty[0], tz[0]);
        Coords c1 = proj_coords(dep0, rx[1], ry[1], rz[1], tx[1], ty[1], tz[1]);
        cjx0 = c0.jx0; cjy0 = c0.jy0;
        cjx1 = c1.jx0; cjy1 = c1.jy0;
        dA00 = quarter_dot(src0 + ((size_t)(c0.iy0*WW + c0.ix0)) * CC, q, rq);
        dA10 = quarter_dot(src0 + ((size_t)(c0.iy0*WW + c0.ix1)) * CC, q, rq);
        dA01 = quarter_dot(src0 + ((size_t)(c0.iy1*WW + c0.ix0)) * CC, q, rq);
        dA11 = quarter_dot(src0 + ((size_t)(c0.iy1*WW + c0.ix1)) * CC, q, rq);
        dB00 = quarter_dot(src1 + ((size_t)(c1.iy0*WW + c1.ix0)) * CC, q, rq);
        dB10 = quarter_dot(src1 + ((size_t)(c1.iy0*WW + c1.ix1)) * CC, q, rq);
        dB01 = quarter_dot(src1 + ((size_t)(c1.iy1*WW + c1.ix0)) * CC, q, rq);
        dB11 = quarter_dot(src1 + ((size_t)(c1.iy1*WW + c1.ix1)) * CC, q, rq);
#pragma unroll
        for (int m = 1; m <= 2; m <<= 1) {
            dA00 += __shfl_xor_sync(0xffffffffu, dA00, m);
            dA10 += __shfl_xor_sync(0xffffffffu, dA10, m);
            dA01 += __shfl_xor_sync(0xffffffffu, dA01, m);
            dA11 += __shfl_xor_sync(0xffffffffu, dA11, m);
            dB00 += __shfl_xor_sync(0xffffffffu, dB00, m);
            dB10 += __shfl_xor_sync(0xffffffffu, dB10, m);
            dB01 += __shfl_xor_sync(0xffffffffu, dB01, m);
            dB11 += __shfl_xor_sync(0xffffffffu, dB11, m);
        }
    }

    float omax0 = -3.4e38f, omax1 = -3.4e38f;

#pragma unroll 1
    for (int k = 0; k < DD/4; k++) {
        int d = q + 4*k;
        float dep = __ldg(dv + (size_t)d * HWW);

        // view 0
        {
            Coords c = proj_coords(dep, rx[0], ry[0], rz[0], tx[0], ty[0], tz[0]);
            if (c.jx0 != cjx0 || c.jy0 != cjy0) {
                cjx0 = c.jx0; cjy0 = c.jy0;
                dA00 = full_dot(src0 + ((size_t)(c.iy0*WW + c.ix0)) * CC, refp);
                dA10 = full_dot(src0 + ((size_t)(c.iy0*WW + c.ix1)) * CC, refp);
                dA01 = full_dot(src0 + ((size_t)(c.iy1*WW + c.ix0)) * CC, refp);
                dA11 = full_dot(src0 + ((size_t)(c.iy1*WW + c.ix1)) * CC, refp);
            }
            float w00 = (1.f - c.fx) * (1.f - c.fy) * c.m00;
            float w10 = c.fx * (1.f - c.fy) * c.m10;
            float w01 = (1.f - c.fx) * c.fy * c.m01;
            float w11 = c.fx * c.fy * c.m11;
            float sim = fmaf(w00, dA00, fmaf(w10, dA10, fmaf(w01, dA01, w11 * dA11))) * 0.0625f;
            sim0out[(size_t)d * HWW] = sim;
            omax0 = fmaxf(omax0, pwl_eval(sim, s_t, s_ab, w2r, fb2));
        }
        // view 1
        {
            Coords c = proj_coords(dep, rx[1], ry[1], rz[1], tx[1], ty[1], tz[1]);
            if (c.jx0 != cjx1 || c.jy0 != cjy1) {
                cjx1 = c.jx0; cjy1 = c.jy0;
                dB00 = full_dot(src1 + ((size_t)(c.iy0*WW + c.ix0)) * CC, refp);
                dB10 = full_dot(src1 + ((size_t)(c.iy0*WW + c.ix1)) * CC, refp);
                dB01 = full_dot(src1 + ((size_t)(c.iy1*WW + c.ix0)) * CC, refp);
                dB11 = full_dot(src1 + ((size_t)(c.iy1*WW + c.ix1)) * CC, refp);
            }
            float w00 = (1.f - c.fx) * (1.f - c.fy) * c.m00;
            float w10 = c.fx * (1.f - c.fy) * c.m10;
            float w01 = (1.f - c.fx) * c.fy * c.m01;
            float w11 = c.fx * c.fy * c.m11;
            float sim = fmaf(w00, dB00, fmaf(w10, dB10, fmaf(w01, dB01, w11 * dB11))) * 0.0625f;
            sim1out[(size_t)d * HWW] = sim;
            omax1 = fmaxf(omax1, pwl_eval(sim, s_t, s_ab, w2r, fb2));
        }
    }

    omax0 = fmaxf(omax0, __shfl_xor_sync(0xffffffffu, omax0, 1));
    omax0 = fmaxf(omax0, __shfl_xor_sync(0xffffffffu, omax0, 2));
    omax1 = fmaxf(omax1, __shfl_xor_sync(0xffffffffu, omax1, 1));
    omax1 = fmaxf(omax1, __shfl_xor_sync(0xffffffffu, omax1, 2));

    float vw0 = 1.f / (1.f + expf(-omax0));   // exact sigmoid
    float vw1 = 1.f / (1.f + expf(-omax1));
    if (q == 0) {
        out[OFF_VW + (size_t)b * NV * HWW + p] = vw0;
        out[OFF_VW + (size_t)b * NV * HWW + HWW + p] = vw1;
    }

    float denom = 1e-5f + vw0 + vw1;
    float* so = g_simil + (size_t)b * DD * HWW + p;
#pragma unroll 1
    for (int k = 0; k < DD/4; k++) {
        int d = q + 4*k;
        float sa = sim0out[(size_t)d * HWW];
        float sb = sim1out[(size_t)d * HWW];
        so[(size_t)d * HWW] = (sa * vw0 + sb * vw1) / denom;   // exact division
    }
}

// ======================= 3x3x3 conv + softmax (2 threads per pixel) =======================
#define DHALF (DD/2)   // 24
__global__ void conv_softmax_kernel(const float* __restrict__ depth_values, float* __restrict__ out) {
    __shared__ float s_k[28];
    if (threadIdx.x < 28) s_k[threadIdx.x] = g_reg[threadIdx.x];
    __syncthreads();

    int tid = blockIdx.x * blockDim.x + threadIdx.x;   // NPIX*2
    int q   = tid & 1;
    int pid = tid >> 1;
    int b = pid / HWW;
    int p = pid - b * HWW;
    int h = p / WW;
    int w = p - h * WW;
    int base = q * DHALF;

    float c[DHALF];
    float bias = s_k[27];
#pragma unroll
    for (int d = 0; d < DHALF; d++) c[d] = bias;

    bool wl = (w > 0), wr = (w < WW - 1);
#pragma unroll 1
    for (int dpi = 0; dpi < DHALF + 2; dpi++) {
        int dp = base - 1 + dpi;
        if (dp < 0 || dp >= DD) continue;
        const float* basep = g_simil + (size_t)(b*DD + dp) * HWW;
        float n[9];
#pragma unroll
        for (int dy = 0; dy < 3; dy++) {
            int hh = h + dy - 1;
            bool vy = (unsigned)hh < (unsigned)HH;
            const float* rowp = basep + hh * WW + w;
            n[dy*3+0] = (vy && wl) ? rowp[-1] : 0.f;
            n[dy*3+1] = vy ? rowp[0] : 0.f;
            n[dy*3+2] = (vy && wr) ? rowp[1] : 0.f;
        }
#pragma unroll
        for (int dz = 0; dz < 3; dz++) {
            int od = dp + 1 - dz;           // output depth receiving this plane via slice dz
            int lod = od - base;
            if (lod < 0 || lod >= DHALF) continue;
            float acc = 0.f;
#pragma unroll
            for (int i = 0; i < 9; i++) acc = fmaf(s_k[dz*9+i], n[i], acc);
            c[lod] += acc;
        }
    }

    // local max + argmax (first-max semantics within half)
    float m = c[0]; int am = base;
#pragma unroll
    for (int d = 1; d < DHALF; d++) if (c[d] > m) { m = c[d]; am = base + d; }

    // exchange with partner lane (q^1)
    float mo  = __shfl_xor_sync(0xffffffffu, m, 1);
    int   amo = __shfl_xor_sync(0xffffffffu, am, 1);
    // global max with first-occurrence tie-breaking (lower half wins ties)
    float m0 = (q == 0) ? m : mo;      // lower-half max
    float m1 = (q == 0) ? mo : m;      // upper-half max
    int   a0 = (q == 0) ? am : amo;
    int   a1 = (q == 0) ? amo : am;
    float gm = (m1 > m0) ? m1 : m0;
    int   ga = (m1 > m0) ? a1 : a0;

    float sum = 0.f;
#pragma unroll
    for (int d = 0; d < DHALF; d++) { float e = __expf(c[d] - gm); c[d] = e; sum += e; }
    sum += __shfl_xor_sync(0xffffffffu, sum, 1);
    float inv = __fdividef(1.f, sum);

    float* pp = out + OFF_PROB + (size_t)b * DD * HWW + p;
#pragma unroll
    for (int d = 0; d < DHALF; d++) pp[(size_t)(base + d) * HWW] = c[d] * inv;

    if (q == 0) {
        out[OFF_DEPTH + pid] = depth_values[(size_t)b * DD * HWW + (size_t)ga * HWW + p];
        out[OFF_CONF + pid] = inv;
    }
}

// ======================= launch =======================
extern "C" void kernel_launch(void* const* d_in, const int* in_sizes, int n_in,
                              void* d_out, int out_size) {
    const float* features     = (const float*)d_in[0];
    const float* proj         = (const float*)d_in[1];
    const float* depth_values = (const float*)d_in[2];
    const float* w0 = (const float*)d_in[3];
    const float* g0 = (const float*)d_in[4];
    const float* b0 = (const float*)d_in[5];
    const float* m0 = (const float*)d_in[6];
    const float* v0 = (const float*)d_in[7];
    const float* w1 = (const float*)d_in[8];
    const float* g1 = (const float*)d_in[9];
    const float* b1 = (const float*)d_in[10];
    const float* m1 = (const float*)d_in[11];
    const float* v1 = (const float*)d_in[12];
    const float* w2 = (const float*)d_in[13];
    const float* b2 = (const float*)d_in[14];
    const float* reg_w = (const float*)d_in[15];
    const float* reg_b = (const float*)d_in[16];
    float* out = (float*)d_out;

    const int TN = BB*VV*HWW;           // transpose elements
    const int THALF = TN / 2;           // split into two launches (ncu captures launch #4)

    prep_kernel<<<1, 256>>>(proj, w0, g0, b0, m0, v0, w1, g1, b1, m1, v1, w2, b2, reg_w, reg_b);
    transpose_kernel<<<(THALF + 255) / 256, 256>>>(features, 0);
    transpose_kernel<<<(TN - THALF + 255) / 256, 256>>>(features, THALF);
    main_kernel<<<(NPIX*4) / 128, 128>>>(depth_values, out);
    conv_softmax_kernel<<<(NPIX*2 + 127) / 128, 128>>>(depth_values, out);
}

// round 9
// speedup vs baseline: 4.1159x; 1.1864x over previous
#include <cuda_runtime.h>
#include <math.h>
#include <float.h>

// Fixed problem shapes
#define BB 2
#define VV 3
#define CC 16
#define HH 128
#define WW 160
#define DD 48
#define HWW (HH*WW)            // 20480
#define NPIX (BB*HWW)          // 40960
#define BDHW (BB*DD*HWW)       // 1966080
#define NV (VV-1)              // 2 source views

// Output layout
#define OFF_DEPTH 0
#define OFF_CONF  (NPIX)
#define OFF_PROB  (2*NPIX)
#define OFF_VW    (2*NPIX + BDHW)

// -------- scratch --------
__device__ float g_feat_t[(size_t)BB*VV*HWW*CC];   // [b][v][h][w][c]
__device__ float g_sim[(size_t)NV*BDHW];           // [view][b][d][h][w]
__device__ float g_simil[BDHW];
__device__ float g_proj[NV*BB*12];
__device__ float g_reg[28];
// PWL representation of the pixelwise MLP (function of scalar sim)
__device__ float g_pwl_t[16];                     // sorted breakpoints
__device__ __align__(16) float g_pwl_ab[17*16];   // per interval i: alpha[8] then beta[8]
__device__ float g_pwl_w2[9];                     // w2[8], b2

// ======================= prep (row-parallel matrices) =======================
__device__ void compose_proj(const float* p, double* out) {
    const float* E = p;
    const float* K = p + 16;
    for (int i = 0; i < 16; i++) out[i] = (double)E[i];
    for (int r = 0; r < 3; r++)
        for (int c = 0; c < 4; c++) {
            double s = 0.0;
            for (int k = 0; k < 3; k++) s += (double)K[r*4+k] * (double)E[k*4+c];
            out[r*4+c] = s;
        }
}

__global__ void prep_kernel(const float* proj,
                            const float* w0, const float* g0, const float* b0,
                            const float* m0, const float* v0,
                            const float* w1, const float* g1, const float* b1,
                            const float* m1, const float* v1,
                            const float* w2, const float* b2,
                            const float* reg_w, const float* reg_b) {
    __shared__ double sh_comp[BB][VV][16];
    __shared__ double sh_M[BB][4][8];      // augmented [refc | I]
    __shared__ double sh_refi[BB][16];
    __shared__ float  sh_fw0[16], sh_fc0[16];
    __shared__ float  sh_fw1[8][16], sh_fc1[8];
    __shared__ int    sh_pos[16];

    int tid = threadIdx.x;

    // stage 1: compose all (b,v) matrices -- 6 threads
    if (tid < BB*VV) {
        int b = tid / VV, v = tid % VV;
        compose_proj(proj + (size_t)(b*VV + v)*2*16, &sh_comp[b][v][0]);
    }
    // BN fold layer 0 -- 16 threads (independent of stage 1)
    if (tid >= 32 && tid < 48) {
        int o = tid - 32;
        double s = (double)g0[o] / sqrt((double)v0[o] + 1e-5);
        sh_fw0[o] = (float)((double)w0[o] * s);
        sh_fc0[o] = (float)((double)b0[o] - (double)m0[o] * s);
    }
    // BN fold layer 1 -- 8 threads
    if (tid >= 64 && tid < 72) {
        int j = tid - 64;
        double s = (double)g1[j] / sqrt((double)v1[j] + 1e-5);
        for (int o = 0; o < 16; o++)
            sh_fw1[j][o] = (float)((double)w1[j*16+o] * s);
        sh_fc1[j] = (float)((double)b1[j] - (double)m1[j] * s);
        g_pwl_w2[j] = w2[j];
    }
    if (tid == 96) {
        g_pwl_w2[8] = b2[0];
        for (int k = 0; k < 27; k++) g_reg[k] = reg_w[k];
        g_reg[27] = reg_b[0];
    }
    __syncthreads();

    // stage 2: build augmented ref matrices -- 8 threads (b, row)
    if (tid < BB*4) {
        int b = tid / 4, r = tid % 4;
        for (int j = 0; j < 4; j++) {
            sh_M[b][r][j]   = sh_comp[b][0][r*4+j];
            sh_M[b][r][4+j] = (r == j) ? 1.0 : 0.0;
        }
    }
    __syncthreads();

    // Gaussian elimination, row-parallel. (For these K*E matrices partial
    // pivoting always selects the diagonal, so no-pivot is arithmetically
    // identical to the pivoted version used in prior passing rounds.)
    for (int col = 0; col < 4; col++) {
        if (tid < BB) {                       // normalize pivot row
            int b = tid;
            double pv = sh_M[b][col][col];
            for (int j = 0; j < 8; j++) sh_M[b][col][j] /= pv;
        }
        __syncthreads();
        if (tid < BB*4) {                     // eliminate other rows
            int b = tid / 4, r = tid % 4;
            if (r != col) {
                double f = sh_M[b][r][col];
                for (int j = 0; j < 8; j++) sh_M[b][r][j] -= f * sh_M[b][col][j];
            }
        }
        __syncthreads();
    }
    if (tid < BB*16) {
        int b = tid / 16, e = tid % 16;
        sh_refi[b][e] = sh_M[b][e/4][4 + (e & 3)];
    }
    __syncthreads();

    // stage 3: P = srcc @ refi -- one thread per output element (2*2*12 = 48)
    if (tid < NV*BB*12) {
        int e  = tid % 12;
        int vb = tid / 12;
        int b  = vb % BB;
        int v  = 1 + vb / BB;
        int r  = e / 4, c = e & 3;
        double s = 0.0;
        for (int k = 0; k < 4; k++) s += sh_comp[b][v][r*4+k] * sh_refi[b][k*4+c];
        float* dst = g_proj + ((v-1)*BB + b)*12;
        if (c < 3) dst[r*3+c]  = (float)s;
        else       dst[9 + r]  = (float)s;
    }

    // breakpoints + sort (serial, tiny)
    if (tid == 0) {
        double t[16]; int ord[16];
        for (int o = 0; o < 16; o++) {
            if (sh_fw0[o] != 0.f) t[o] = -(double)sh_fc0[o] / (double)sh_fw0[o];
            else                  t[o] = DBL_MAX;
            ord[o] = o;
        }
        for (int i = 1; i < 16; i++) {
            int k = ord[i]; double tv = t[k]; int j = i - 1;
            while (j >= 0 && t[ord[j]] > tv) { ord[j+1] = ord[j]; j--; }
            ord[j+1] = k;
        }
        for (int k = 0; k < 16; k++) {
            double tv = t[ord[k]];
            g_pwl_t[k] = (tv >= DBL_MAX) ? FLT_MAX : (float)tv;
            sh_pos[ord[k]] = k;
        }
    }
    __syncthreads();

    // parallel PWL table build: one thread per (interval i, unit j)
    if (tid < 17*8) {
        int i = tid / 8;
        int j = tid % 8;
        double alpha = 0.0, beta = (double)sh_fc1[j];
        for (int o = 0; o < 16; o++) {
            bool active;
            float fw0o = sh_fw0[o];
            if (fw0o > 0.f)      active = (sh_pos[o] < i);
            else if (fw0o < 0.f) active = (sh_pos[o] >= i);
            else                 active = (sh_fc0[o] > 0.f);
            if (active) {
                alpha += (double)sh_fw1[j][o] * (double)fw0o;
                beta  += (double)sh_fw1[j][o] * (double)sh_fc0[o];
            }
        }
        g_pwl_ab[i*16 + j]     = (float)alpha;
        g_pwl_ab[i*16 + 8 + j] = (float)beta;
    }
}

// ======================= feature transpose to [b][v][h][w][c] =======================
__global__ void transpose_kernel(const float* __restrict__ feat, int off) {
    int idx = off + blockIdx.x * blockDim.x + threadIdx.x;
    if (idx >= BB*VV*HWW) return;
    int p  = idx % HWW;
    int bv = idx / HWW;
    const float* src = feat + (size_t)bv * CC * HWW + p;
    float v[CC];
#pragma unroll
    for (int c = 0; c < CC; c++) v[c] = src[(size_t)c * HWW];
    float4* dst = (float4*)(g_feat_t + ((size_t)bv * HWW + p) * CC);
    dst[0] = make_float4(v[0],  v[1],  v[2],  v[3]);
    dst[1] = make_float4(v[4],  v[5],  v[6],  v[7]);
    dst[2] = make_float4(v[8],  v[9],  v[10], v[11]);
    dst[3] = make_float4(v[12], v[13], v[14], v[15]);
}

// helper: coords for one depth (indices/valid via integer ops)
struct Coords {
    float fx, fy;
    int jx0, jy0;
    int ix0, ix1, iy0, iy1;
    float m00, m10, m01, m11;
};
__device__ __forceinline__ Coords proj_coords(float dep, float rx, float ry, float rz,
                                              float tx, float ty, float tz) {
    Coords c;
    float X = fmaf(rx, dep, tx);
    float Y = fmaf(ry, dep, ty);
    float Z = fmaf(rz, dep, tz);
    float px = X / Z;            // exact IEEE division (argmax-sensitive)
    float py = Y / Z;
    float x0f = floorf(px), y0f = floorf(py);
    c.fx = px - x0f; c.fy = py - y0f;
    c.jx0 = __float2int_rd(px);
    c.jy0 = __float2int_rd(py);
    bool bx0 = (c.jx0 >= 0)  && (c.jx0 <  WW);
    bool bx1 = (c.jx0 >= -1) && (c.jx0 <  WW-1);
    bool by0 = (c.jy0 >= 0)  && (c.jy0 <  HH);
    bool by1 = (c.jy0 >= -1) && (c.jy0 <  HH-1);
    c.m00 = (bx0 && by0) ? 1.f : 0.f;
    c.m10 = (bx1 && by0) ? 1.f : 0.f;
    c.m01 = (bx0 && by1) ? 1.f : 0.f;
    c.m11 = (bx1 && by1) ? 1.f : 0.f;
    c.ix0 = min(max(c.jx0,     0), WW-1);
    c.ix1 = min(max(c.jx0 + 1, 0), WW-1);
    c.iy0 = min(max(c.jy0,     0), HH-1);
    c.iy1 = min(max(c.jy0 + 1, 0), HH-1);
    return c;
}

__device__ __forceinline__ float full_dot(const float* fp, const float* rp) {
    float part[4];
#pragma unroll
    for (int qq = 0; qq < 4; qq++) {
        float4 f = ((const float4*)fp)[qq];
        float4 r = ((const float4*)rp)[qq];
        part[qq] = fmaf(f.x, r.x, fmaf(f.y, r.y, fmaf(f.z, r.z, f.w * r.w)));
    }
    return (part[0] + part[1]) + (part[2] + part[3]);
}

__device__ __forceinline__ float quarter_dot(const float* fp, int q, float4 rq) {
    float4 f = ((const float4*)fp)[q];
    return fmaf(f.x, rq.x, fmaf(f.y, rq.y, fmaf(f.z, rq.z, f.w * rq.w)));
}

// PWL MLP eval -- breakpoints/w2 in registers, ab rows via LDS.128
__device__ __forceinline__ float pwl_eval(float s, const float* th, const float* s_ab,
                                          const float* w2r, float fb2) {
    int idx = 0;
#pragma unroll
    for (int i = 0; i < 16; i++) idx += (s > th[i]) ? 1 : 0;
    const float4* abv = (const float4*)(s_ab + idx * 16);
    float4 A0 = abv[0], A1 = abv[1], B0 = abv[2], B1 = abv[3];
    float ov = fb2;
    ov = fmaf(w2r[0], fmaxf(fmaf(A0.x, s, B0.x), 0.f), ov);
    ov = fmaf(w2r[1], fmaxf(fmaf(A0.y, s, B0.y), 0.f), ov);
    ov = fmaf(w2r[2], fmaxf(fmaf(A0.z, s, B0.z), 0.f), ov);
    ov = fmaf(w2r[3], fmaxf(fmaf(A0.w, s, B0.w), 0.f), ov);
    ov = fmaf(w2r[4], fmaxf(fmaf(A1.x, s, B1.x), 0.f), ov);
    ov = fmaf(w2r[5], fmaxf(fmaf(A1.y, s, B1.y), 0.f), ov);
    ov = fmaf(w2r[6], fmaxf(fmaf(A1.z, s, B1.z), 0.f), ov);
    ov = fmaf(w2r[7], fmaxf(fmaf(A1.w, s, B1.w), 0.f), ov);
    return ov;
}

// ======================= fused: gather(2 views) + PWL-MLP + sigmoid + combine =======================
__global__ void __launch_bounds__(128, 6)
main_kernel(const float* __restrict__ depth_values, float* __restrict__ out) {
    __shared__ __align__(16) float s_ab[17*16];
    for (int i = threadIdx.x; i < 17*16; i += blockDim.x) s_ab[i] = g_pwl_ab[i];
    __syncthreads();

    int tid = blockIdx.x * blockDim.x + threadIdx.x;   // NPIX*4
    int q   = tid & 3;
    int pid = tid >> 2;
    int b = pid / HWW;
    int p = pid - b * HWW;
    int h = p / WW;
    int w = p - h * WW;

    const float* refp = g_feat_t + ((size_t)(b*VV + 0) * HWW + p) * CC;
    float4 rq = ((const float4*)refp)[q];

    float rx[2], ry[2], rz[2], tx[2], ty[2], tz[2];
#pragma unroll
    for (int v = 0; v < 2; v++) {
        const float* pr = g_proj + (v*BB + b) * 12;
        float fw = (float)w, fh = (float)h;
        rx[v] = pr[0]*fw + pr[1]*fh + pr[2];
        ry[v] = pr[3]*fw + pr[4]*fh + pr[5];
        rz[v] = pr[6]*fw + pr[7]*fh + pr[8];
        tx[v] = pr[9]; ty[v] = pr[10]; tz[v] = pr[11];
    }
    const float* src0 = g_feat_t + (size_t)(b*VV + 1) * HWW * CC;
    const float* src1 = g_feat_t + (size_t)(b*VV + 2) * HWW * CC;
    const float* dv   = depth_values + (size_t)b * DD * HWW + p;
    float* sim0out    = g_sim + (size_t)b * DD * HWW + p;
    float* sim1out    = g_sim + (size_t)BDHW + (size_t)b * DD * HWW + p;

    // PWL constants in registers
    float th[16];
#pragma unroll
    for (int i = 0; i < 16; i++) th[i] = g_pwl_t[i];
    float w2r[8];
#pragma unroll
    for (int j = 0; j < 8; j++) w2r[j] = g_pwl_w2[j];
    float fb2 = g_pwl_w2[8];

    // ---- setup: cooperative corner dots at depth 0 for both views ----
    int cjx0, cjy0, cjx1, cjy1;
    float dA00, dA10, dA01, dA11;
    float dB00, dB10, dB01, dB11;
    {
        float dep0 = __ldg(dv);
        Coords c0 = proj_coords(dep0, rx[0], ry[0], rz[0], tx[0], ty[0], tz[0]);
        Coords c1 = proj_coords(dep0, rx[1], ry[1], rz[1], tx[1], ty[1], tz[1]);
        cjx0 = c0.jx0; cjy0 = c0.jy0;
        cjx1 = c1.jx0; cjy1 = c1.jy0;
        dA00 = quarter_dot(src0 + ((size_t)(c0.iy0*WW + c0.ix0)) * CC, q, rq);
        dA10 = quarter_dot(src0 + ((size_t)(c0.iy0*WW + c0.ix1)) * CC, q, rq);
        dA01 = quarter_dot(src0 + ((size_t)(c0.iy1*WW + c0.ix0)) * CC, q, rq);
        dA11 = quarter_dot(src0 + ((size_t)(c0.iy1*WW + c0.ix1)) * CC, q, rq);
        dB00 = quarter_dot(src1 + ((size_t)(c1.iy0*WW + c1.ix0)) * CC, q, rq);
        dB10 = quarter_dot(src1 + ((size_t)(c1.iy0*WW + c1.ix1)) * CC, q, rq);
        dB01 = quarter_dot(src1 + ((size_t)(c1.iy1*WW + c1.ix0)) * CC, q, rq);
        dB11 = quarter_dot(src1 + ((size_t)(c1.iy1*WW + c1.ix1)) * CC, q, rq);
#pragma unroll
        for (int m = 1; m <= 2; m <<= 1) {
            dA00 += __shfl_xor_sync(0xffffffffu, dA00, m);
            dA10 += __shfl_xor_sync(0xffffffffu, dA10, m);
            dA01 += __shfl_xor_sync(0xffffffffu, dA01, m);
            dA11 += __shfl_xor_sync(0xffffffffu, dA11, m);
            dB00 += __shfl_xor_sync(0xffffffffu, dB00, m);
            dB10 += __shfl_xor_sync(0xffffffffu, dB10, m);
            dB01 += __shfl_xor_sync(0xffffffffu, dB01, m);
            dB11 += __shfl_xor_sync(0xffffffffu, dB11, m);
        }
    }

    float omax0 = -3.4e38f, omax1 = -3.4e38f;

    const int STR = 4 * HWW;               // depth stride for this lane
    const float* dvp = dv + q * HWW;
    float* s0p = sim0out + q * HWW;
    float* s1p = sim1out + q * HWW;

#pragma unroll 1
    for (int k = 0; k < DD/4; k++) {
        float dep = __ldg(dvp);

        // view 0
        {
            Coords c = proj_coords(dep, rx[0], ry[0], rz[0], tx[0], ty[0], tz[0]);
            if (c.jx0 != cjx0 || c.jy0 != cjy0) {
                cjx0 = c.jx0; cjy0 = c.jy0;
                dA00 = full_dot(src0 + ((size_t)(c.iy0*WW + c.ix0)) * CC, refp);
                dA10 = full_dot(src0 + ((size_t)(c.iy0*WW + c.ix1)) * CC, refp);
                dA01 = full_dot(src0 + ((size_t)(c.iy1*WW + c.ix0)) * CC, refp);
                dA11 = full_dot(src0 + ((size_t)(c.iy1*WW + c.ix1)) * CC, refp);
            }
            float w00 = (1.f - c.fx) * (1.f - c.fy) * c.m00;
            float w10 = c.fx * (1.f - c.fy) * c.m10;
            float w01 = (1.f - c.fx) * c.fy * c.m01;
            float w11 = c.fx * c.fy * c.m11;
            float sim = fmaf(w00, dA00, fmaf(w10, dA10, fmaf(w01, dA01, w11 * dA11))) * 0.0625f;
            *s0p = sim;
            omax0 = fmaxf(omax0, pwl_eval(sim, th, s_ab, w2r, fb2));
        }
        // view 1
        {
            Coords c = proj_coords(dep, rx[1], ry[1], rz[1], tx[1], ty[1], tz[1]);
            if (c.jx0 != cjx1 || c.jy0 != cjy1) {
                cjx1 = c.jx0; cjy1 = c.jy0;
                dB00 = full_dot(src1 + ((size_t)(c.iy0*WW + c.ix0)) * CC, refp);
                dB10 = full_dot(src1 + ((size_t)(c.iy0*WW + c.ix1)) * CC, refp);
                dB01 = full_dot(src1 + ((size_t)(c.iy1*WW + c.ix0)) * CC, refp);
                dB11 = full_dot(src1 + ((size_t)(c.iy1*WW + c.ix1)) * CC, refp);
            }
            float w00 = (1.f - c.fx) * (1.f - c.fy) * c.m00;
            float w10 = c.fx * (1.f - c.fy) * c.m10;
            float w01 = (1.f - c.fx) * c.fy * c.m01;
            float w11 = c.fx * c.fy * c.m11;
            float sim = fmaf(w00, dB00, fmaf(w10, dB10, fmaf(w01, dB01, w11 * dB11))) * 0.0625f;
            *s1p = sim;
            omax1 = fmaxf(omax1, pwl_eval(sim, th, s_ab, w2r, fb2));
        }

        dvp += STR; s0p += STR; s1p += STR;
    }

    omax0 = fmaxf(omax0, __shfl_xor_sync(0xffffffffu, omax0, 1));
    omax0 = fmaxf(omax0, __shfl_xor_sync(0xffffffffu, omax0, 2));
    omax1 = fmaxf(omax1, __shfl_xor_sync(0xffffffffu, omax1, 1));
    omax1 = fmaxf(omax1, __shfl_xor_sync(0xffffffffu, omax1, 2));

    float vw0 = 1.f / (1.f + expf(-omax0));   // exact sigmoid
    float vw1 = 1.f / (1.f + expf(-omax1));
    if (q == 0) {
        out[OFF_VW + (size_t)b * NV * HWW + p] = vw0;
        out[OFF_VW + (size_t)b * NV * HWW + HWW + p] = vw1;
    }

    float denom = 1e-5f + vw0 + vw1;
    const float* r0p = sim0out + q * HWW;
    const float* r1p = sim1out + q * HWW;
    float* sop = g_simil + (size_t)b * DD * HWW + p + q * HWW;
#pragma unroll 1
    for (int k = 0; k < DD/4; k++) {
        float sa = *r0p;
        float sb = *r1p;
        *sop = (sa * vw0 + sb * vw1) / denom;   // exact division
        r0p += STR; r1p += STR; sop += STR;
    }
}

// ======================= 3x3x3 conv + softmax (4 threads per pixel) =======================
#define DQ (DD/4)   // 12
__global__ void conv_softmax_kernel(const float* __restrict__ depth_values, float* __restrict__ out) {
    __shared__ float s_k[28];
    if (threadIdx.x < 28) s_k[threadIdx.x] = g_reg[threadIdx.x];
    __syncthreads();

    int tid = blockIdx.x * blockDim.x + threadIdx.x;   // NPIX*4
    int q   = tid & 3;
    int pid = tid >> 2;
    int b = pid / HWW;
    int p = pid - b * HWW;
    int h = p / WW;
    int w = p - h * WW;
    int base = q * DQ;

    float c[DQ];
    float bias = s_k[27];
#pragma unroll
    for (int d = 0; d < DQ; d++) c[d] = bias;

    bool wl = (w > 0), wr = (w < WW - 1);
#pragma unroll 1
    for (int dpi = 0; dpi < DQ + 2; dpi++) {
        int dp = base - 1 + dpi;
        if ((unsigned)dp >= (unsigned)DD) continue;
        const float* basep = g_simil + (size_t)(b*DD + dp) * HWW;
        float n[9];
#pragma unroll
        for (int dy = 0; dy < 3; dy++) {
            int hh = h + dy - 1;
            bool vy = (unsigned)hh < (unsigned)HH;
            const float* rowp = basep + hh * WW + w;
            n[dy*3+0] = (vy && wl) ? rowp[-1] : 0.f;
            n[dy*3+1] = vy ? rowp[0] : 0.f;
            n[dy*3+2] = (vy && wr) ? rowp[1] : 0.f;
        }
#pragma unroll
        for (int dz = 0; dz < 3; dz++) {
            int od = dp + 1 - dz;
            int lod = od - base;
            if (lod < 0 || lod >= DQ) continue;
            float acc = 0.f;
#pragma unroll
            for (int i = 0; i < 9; i++) acc = fmaf(s_k[dz*9+i], n[i], acc);
            c[lod] += acc;
        }
    }

    // local first-max + argmax
    float m = c[0]; int am = base;
#pragma unroll
    for (int d = 1; d < DQ; d++) if (c[d] > m) { m = c[d]; am = base + d; }

    // merge 4 lanes: lexicographic (max value, min index) == global first-max
#pragma unroll
    for (int mask = 1; mask <= 2; mask <<= 1) {
        float mo  = __shfl_xor_sync(0xffffffffu, m, mask);
        int   amo = __shfl_xor_sync(0xffffffffu, am, mask);
        if (mo > m || (mo == m && amo < am)) { m = mo; am = amo; }
    }

    float sum = 0.f;
#pragma unroll
    for (int d = 0; d < DQ; d++) { float e = __expf(c[d] - m); c[d] = e; sum += e; }
    sum += __shfl_xor_sync(0xffffffffu, sum, 1);
    sum += __shfl_xor_sync(0xffffffffu, sum, 2);
    float inv = __fdividef(1.f, sum);

    float* pp = out + OFF_PROB + (size_t)b * DD * HWW + p;
#pragma unroll
    for (int d = 0; d < DQ; d++) pp[(size_t)(base + d) * HWW] = c[d] * inv;

    if (q == 0) {
        out[OFF_DEPTH + pid] = depth_values[(size_t)b * DD * HWW + (size_t)am * HWW + p];
        out[OFF_CONF + pid] = inv;
    }
}

// ======================= launch =======================
extern "C" void kernel_launch(void* const* d_in, const int* in_sizes, int n_in,
                              void* d_out, int out_size) {
    const float* features     = (const float*)d_in[0];
    const float* proj         = (const float*)d_in[1];
    const float* depth_values = (const float*)d_in[2];
    const float* w0 = (const float*)d_in[3];
    const float* g0 = (const float*)d_in[4];
    const float* b0 = (const float*)d_in[5];
    const float* m0 = (const float*)d_in[6];
    const float* v0 = (const float*)d_in[7];
    const float* w1 = (const float*)d_in[8];
    const float* g1 = (const float*)d_in[9];
    const float* b1 = (const float*)d_in[10];
    const float* m1 = (const float*)d_in[11];
    const float* v1 = (const float*)d_in[12];
    const float* w2 = (const float*)d_in[13];
    const float* b2 = (const float*)d_in[14];
    const float* reg_w = (const float*)d_in[15];
    const float* reg_b = (const float*)d_in[16];
    float* out = (float*)d_out;

    const int TN = BB*VV*HWW;
    const int THALF = TN / 2;        // two transpose launches keep main as launch #4 for ncu

    prep_kernel<<<1, 256>>>(proj, w0, g0, b0, m0, v0, w1, g1, b1, m1, v1, w2, b2, reg_w, reg_b);
    transpose_kernel<<<(THALF + 255) / 256, 256>>>(features, 0);
    transpose_kernel<<<(TN - THALF + 255) / 256, 256>>>(features, THALF);
    main_kernel<<<(NPIX*4) / 128, 128>>>(depth_values, out);
    conv_softmax_kernel<<<(NPIX*4 + 127) / 128, 128>>>(depth_values, out);
}